// round 7
// baseline (speedup 1.0000x reference)
#include <cuda_runtime.h>
#include <cstdint>
#include <cstddef>

// Problem: V=35, E=256, H=512, K=128, VS=128, N=64, T=2000, L=300, START=33
#define NBLK 128
#define NTHR 512

#define N_B   64
#define T_T   2000
#define T4    500        // T_T/4 float4 per transposed row
#define L_L   300
#define E_E   256
#define H_H   512
#define KD    128
#define V_V   35
#define K1    640        // ctx(128)+h1(512)
#define K2    640        // h1(512)+h2(128)
#define START_TOK 33

// ---------------- device scratch (static: no allocation) ----------------
__device__ __align__(16) float g_keyT[(size_t)N_B * KD * T_T];   // [n][d][t]
__device__ __align__(16) float g_valT[(size_t)N_B * KD * T_T];   // [n][d][t]
__device__ __align__(16) float g_W1q[K1 * H_H * 4];              // [(k*512+j)*4+g]
__device__ __align__(16) float g_W2q[K2 * KD * 4];               // [(k*128+j)*4+g]
__device__ __align__(16) float g_embW1[V_V * H_H * 4];           // [(tok*512+j)*4+g]
__device__ __align__(16) float g_b2[KD * 4];                     // bih2+bhh2 per (j,gate)
__device__ __align__(16) float g_x1[2][K1 * N_B];                // [buf][k][n] k<128 ctx, k>=128 h1
__device__ __align__(16) float g_x2[2][K2 * N_B];                // [buf][k][n] k<512 h1, k>=512 h2
__device__ __align__(16) float g_c1[H_H * N_B];
__device__ __align__(16) float g_c2[KD * N_B];

__device__ unsigned g_bar_cnt;
__device__ volatile unsigned g_bar_gen;

__device__ __forceinline__ float sigf(float x) { return 1.0f / (1.0f + __expf(-x)); }

__device__ __forceinline__ unsigned long long packf2(float a, float b) {
    float2 f = make_float2(a, b);
    return *reinterpret_cast<unsigned long long*>(&f);
}
__device__ __forceinline__ unsigned long long f2fma(unsigned long long a,
                                                    unsigned long long b,
                                                    unsigned long long c) {
    unsigned long long d;
    asm("fma.rn.f32x2 %0, %1, %2, %3;" : "=l"(d) : "l"(a), "l"(b), "l"(c));
    return d;
}

// grid-wide barrier; __threadfence (gpu scope) flushes/invalidates L1D on sm_103a
__device__ __forceinline__ void gridbar() {
    __syncthreads();
    __threadfence();
    if (threadIdx.x == 0) {
        unsigned gen = g_bar_gen;
        if (atomicAdd(&g_bar_cnt, 1u) == NBLK - 1) {
            g_bar_cnt = 0;
            __threadfence();
            g_bar_gen = gen + 1;
        } else {
            while (g_bar_gen == gen) { __nanosleep(128); }
        }
    }
    __syncthreads();
    __threadfence();
}

__global__ __launch_bounds__(NTHR, 1) void mega(
    const float* __restrict__ key, const float* __restrict__ values,
    const int* __restrict__ lens, const int* __restrict__ text,
    const float* __restrict__ emb,
    const float* __restrict__ Wih1, const float* __restrict__ Whh1,
    const float* __restrict__ bih1, const float* __restrict__ bhh1,
    const float* __restrict__ Wih2, const float* __restrict__ Whh2,
    const float* __restrict__ bih2, const float* __restrict__ bhh2,
    const float* __restrict__ bout, float* __restrict__ out)
{
    __shared__ __align__(16) float cb[8 * 4 * 4 * 64];  // 32 KB combine / transpose tile
    __shared__ __align__(16) float es[2048];            // 8 KB softmax weights
    __shared__ __align__(16) float h2s[128];
    __shared__ __align__(16) float ctxs[128];
    __shared__ float red[32];

    const int tid = threadIdx.x;
    const int b = blockIdx.x;
    const int wid = tid >> 5, lane = tid & 31;

    // ======================= PREP =======================
    // zero state
    for (int i = b * NTHR + tid; i < 2 * K1 * N_B; i += NBLK * NTHR) ((float*)g_x1)[i] = 0.0f;
    for (int i = b * NTHR + tid; i < 2 * K2 * N_B; i += NBLK * NTHR) ((float*)g_x2)[i] = 0.0f;
    for (int i = b * NTHR + tid; i < H_H * N_B; i += NBLK * NTHR) g_c1[i] = 0.0f;
    for (int i = b * NTHR + tid; i < KD * N_B; i += NBLK * NTHR) g_c2[i] = 0.0f;

    // W1q: [(k*512+j)*4+g]; k<128 -> Wih1[:,256+k] (ctx), k>=128 -> Whh1
    for (int idx = b * NTHR + tid; idx < K1 * H_H; idx += NBLK * NTHR) {
        int k = idx / H_H, j = idx % H_H;
        float4 w;
        float* wp = reinterpret_cast<float*>(&w);
#pragma unroll
        for (int g = 0; g < 4; g++) {
            int row = g * H_H + j;
            wp[g] = (k < 128) ? Wih1[(size_t)row * 384 + 256 + k]
                              : Whh1[(size_t)row * 512 + (k - 128)];
        }
        *reinterpret_cast<float4*>(&g_W1q[(size_t)idx * 4]) = w;
    }
    // W2q: k<512 -> Wih2, k>=512 -> Whh2
    for (int idx = b * NTHR + tid; idx < K2 * KD; idx += NBLK * NTHR) {
        int k = idx / KD, j = idx % KD;
        float4 w;
        float* wp = reinterpret_cast<float*>(&w);
#pragma unroll
        for (int g = 0; g < 4; g++) {
            int row = g * KD + j;
            wp[g] = (k < 512) ? Wih2[(size_t)row * 512 + k]
                              : Whh2[(size_t)row * 128 + (k - 512)];
        }
        *reinterpret_cast<float4*>(&g_W2q[(size_t)idx * 4]) = w;
    }
    // b2
    for (int j = b * NTHR + tid; j < KD; j += NBLK * NTHR) {
        float4 w;
        w.x = bih2[j] + bhh2[j];
        w.y = bih2[j + 128] + bhh2[j + 128];
        w.z = bih2[j + 256] + bhh2[j + 256];
        w.w = bih2[j + 384] + bhh2[j + 384];
        *reinterpret_cast<float4*>(&g_b2[j * 4]) = w;
    }
    // embW1: warp per (tok,j): emb[tok]·Wih1[row][0:256] + bih1+bhh1, all 4 gates
    for (int it = b * 16 + wid; it < V_V * H_H; it += NBLK * 16) {
        int tok = it / H_H, j = it % H_H;
        const float4* e4 = reinterpret_cast<const float4*>(emb + (size_t)tok * E_E);
        float4 ea = e4[lane], eb = e4[lane + 32];
        float a[4];
#pragma unroll
        for (int g = 0; g < 4; g++) {
            int row = g * H_H + j;
            const float4* w4 = reinterpret_cast<const float4*>(Wih1 + (size_t)row * 384);
            float4 wa = w4[lane], wb = w4[lane + 32];
            a[g] = ea.x * wa.x + ea.y * wa.y + ea.z * wa.z + ea.w * wa.w
                 + eb.x * wb.x + eb.y * wb.y + eb.z * wb.z + eb.w * wb.w;
        }
#pragma unroll
        for (int s = 16; s > 0; s >>= 1) {
#pragma unroll
            for (int g = 0; g < 4; g++) a[g] += __shfl_xor_sync(0xffffffffu, a[g], s);
        }
        if (lane == 0) {
            float4 r;
            r.x = a[0] + bih1[j] + bhh1[j];
            r.y = a[1] + bih1[j + 512] + bhh1[j + 512];
            r.z = a[2] + bih1[j + 1024] + bhh1[j + 1024];
            r.w = a[3] + bih1[j + 1536] + bhh1[j + 1536];
            *reinterpret_cast<float4*>(&g_embW1[(size_t)it * 4]) = r;
        }
    }
    // transpose key/values -> [n][d][t], 32x32 tiles (63 t-tiles x 4 d-tiles per n)
    {
        const int tx = tid & 31, ty = tid >> 5;  // ty 0..15
        for (int tileid = b; tileid < 2 * N_B * 63 * 4; tileid += NBLK) {
            int rem = tileid;
            const float* src = key;
            float* dst = g_keyT;
            if (rem >= N_B * 63 * 4) { rem -= N_B * 63 * 4; src = values; dst = g_valT; }
            int n = rem / (63 * 4);
            int r2 = rem % (63 * 4);
            int t0 = (r2 / 4) * 32, d0 = (r2 % 4) * 32;
            __syncthreads();
#pragma unroll
            for (int r = 0; r < 32; r += 16) {
                int t = t0 + r + ty;
                cb[(r + ty) * 33 + tx] =
                    (t < T_T) ? src[((size_t)n * T_T + t) * KD + d0 + tx] : 0.0f;
            }
            __syncthreads();
#pragma unroll
            for (int r = 0; r < 32; r += 16) {
                int t = t0 + tx;
                if (t < T_T)
                    dst[((size_t)n * KD + d0 + r + ty) * T_T + t] = cb[tx * 33 + (r + ty)];
            }
        }
        __syncthreads();
    }

    gridbar();

    // ======================= MAIN LOOP =======================
    const int ks = tid >> 6;         // 0..7  (K split)
    const int jl = (tid >> 4) & 3;   // 0..3  (j within block)
    const int nq = tid & 15;         // 0..15 (n quad)

    for (int step = 0; step < L_L; step++) {
        const int cur = step & 1, nxt = cur ^ 1;

        // ---- Phase A: gemm1 (2048x64, K=640) + cell1, block owns j = 4b..4b+3 ----
        {
            const int j = b * 4 + jl;
            const float* __restrict__ x = g_x1[cur];
            unsigned long long acc[8];
#pragma unroll
            for (int i = 0; i < 8; i++) acc[i] = 0ull;
#pragma unroll 4
            for (int i = 0; i < 80; i++) {
                const int k = ks * 80 + i;
                const float4 w4 = *reinterpret_cast<const float4*>(&g_W1q[((size_t)k * 512 + j) * 4]);
                const float4 xv = *reinterpret_cast<const float4*>(&x[k * 64 + nq * 4]);
                const unsigned long long xlo = packf2(xv.x, xv.y);
                const unsigned long long xhi = packf2(xv.z, xv.w);
                acc[0] = f2fma(packf2(w4.x, w4.x), xlo, acc[0]);
                acc[1] = f2fma(packf2(w4.x, w4.x), xhi, acc[1]);
                acc[2] = f2fma(packf2(w4.y, w4.y), xlo, acc[2]);
                acc[3] = f2fma(packf2(w4.y, w4.y), xhi, acc[3]);
                acc[4] = f2fma(packf2(w4.z, w4.z), xlo, acc[4]);
                acc[5] = f2fma(packf2(w4.z, w4.z), xhi, acc[5]);
                acc[6] = f2fma(packf2(w4.w, w4.w), xlo, acc[6]);
                acc[7] = f2fma(packf2(w4.w, w4.w), xhi, acc[7]);
            }
#pragma unroll
            for (int g = 0; g < 4; g++) {
                float2 lo = *reinterpret_cast<float2*>(&acc[g * 2]);
                float2 hi = *reinterpret_cast<float2*>(&acc[g * 2 + 1]);
                *reinterpret_cast<float4*>(&cb[((ks * 4 + jl) * 4 + g) * 64 + nq * 4]) =
                    make_float4(lo.x, lo.y, hi.x, hi.y);
            }
            __syncthreads();
            if (tid < 256) {
                const int jl2 = tid >> 6, n = tid & 63;
                const int j2 = b * 4 + jl2;
                const int tok = (step == 0) ? START_TOK : text[n * L_L + step - 1];
                const float4 g0 = *reinterpret_cast<const float4*>(&g_embW1[((size_t)tok * 512 + j2) * 4]);
                float gi = g0.x, gf = g0.y, gg = g0.z, go = g0.w;
#pragma unroll
                for (int s = 0; s < 8; s++) {
                    gi += cb[((s * 4 + jl2) * 4 + 0) * 64 + n];
                    gf += cb[((s * 4 + jl2) * 4 + 1) * 64 + n];
                    gg += cb[((s * 4 + jl2) * 4 + 2) * 64 + n];
                    go += cb[((s * 4 + jl2) * 4 + 3) * 64 + n];
                }
                float c = g_c1[j2 * 64 + n];
                c = sigf(gf) * c + sigf(gi) * tanhf(gg);
                float h = sigf(go) * tanhf(c);
                g_c1[j2 * 64 + n] = c;
                g_x1[nxt][(128 + j2) * 64 + n] = h;  // h1 -> next-step gates1
                g_x2[cur][j2 * 64 + n] = h;          // h1 -> this-step gates2
            }
        }
        gridbar();

        // ---- Phase B: gemm2 (512x64, K=640) + cell2, blocks 0..31 own j = 4b..4b+3 ----
        if (b < 32) {
            const int j = b * 4 + jl;
            const float* __restrict__ x = g_x2[cur];
            unsigned long long acc[8];
#pragma unroll
            for (int i = 0; i < 8; i++) acc[i] = 0ull;
#pragma unroll 4
            for (int i = 0; i < 80; i++) {
                const int k = ks * 80 + i;
                const float4 w4 = *reinterpret_cast<const float4*>(&g_W2q[((size_t)k * 128 + j) * 4]);
                const float4 xv = *reinterpret_cast<const float4*>(&x[k * 64 + nq * 4]);
                const unsigned long long xlo = packf2(xv.x, xv.y);
                const unsigned long long xhi = packf2(xv.z, xv.w);
                acc[0] = f2fma(packf2(w4.x, w4.x), xlo, acc[0]);
                acc[1] = f2fma(packf2(w4.x, w4.x), xhi, acc[1]);
                acc[2] = f2fma(packf2(w4.y, w4.y), xlo, acc[2]);
                acc[3] = f2fma(packf2(w4.y, w4.y), xhi, acc[3]);
                acc[4] = f2fma(packf2(w4.z, w4.z), xlo, acc[4]);
                acc[5] = f2fma(packf2(w4.z, w4.z), xhi, acc[5]);
                acc[6] = f2fma(packf2(w4.w, w4.w), xlo, acc[6]);
                acc[7] = f2fma(packf2(w4.w, w4.w), xhi, acc[7]);
            }
#pragma unroll
            for (int g = 0; g < 4; g++) {
                float2 lo = *reinterpret_cast<float2*>(&acc[g * 2]);
                float2 hi = *reinterpret_cast<float2*>(&acc[g * 2 + 1]);
                *reinterpret_cast<float4*>(&cb[((ks * 4 + jl) * 4 + g) * 64 + nq * 4]) =
                    make_float4(lo.x, lo.y, hi.x, hi.y);
            }
            __syncthreads();
            if (tid < 256) {
                const int jl2 = tid >> 6, n = tid & 63;
                const int j2 = b * 4 + jl2;
                const float4 bb = *reinterpret_cast<const float4*>(&g_b2[j2 * 4]);
                float gi = bb.x, gf = bb.y, gg = bb.z, go = bb.w;
#pragma unroll
                for (int s = 0; s < 8; s++) {
                    gi += cb[((s * 4 + jl2) * 4 + 0) * 64 + n];
                    gf += cb[((s * 4 + jl2) * 4 + 1) * 64 + n];
                    gg += cb[((s * 4 + jl2) * 4 + 2) * 64 + n];
                    go += cb[((s * 4 + jl2) * 4 + 3) * 64 + n];
                }
                float c = g_c2[j2 * 64 + n];
                c = sigf(gf) * c + sigf(gi) * tanhf(gg);
                float h = sigf(go) * tanhf(c);
                g_c2[j2 * 64 + n] = c;
                g_x2[nxt][(512 + j2) * 64 + n] = h;  // h2 -> next-step gates2 + this-step attn
            }
        }
        gridbar();

        // ---- Phase C: attention + logits, blocks 0..63 (block = batch element) ----
        if (b < 64) {
            const int n = b;
            if (tid < 128) h2s[tid] = g_x2[nxt][(512 + tid) * 64 + n];
            for (int i = tid; i < 2048; i += NTHR) es[i] = 0.0f;
            __syncthreads();

            const int len = lens[n];
            const int t0 = tid * 4;

            // energy: thread owns 4 timesteps, coalesced loads from keyT, no reduction
            float lmax = -3e38f;
            if (t0 < len) {
                const float4* kT = reinterpret_cast<const float4*>(g_keyT + (size_t)n * KD * T_T);
                unsigned long long a0 = 0ull, a1 = 0ull;
#pragma unroll 4
                for (int d = 0; d < 128; d++) {
                    const float hv = h2s[d];
                    const float4 kv = kT[(size_t)d * T4 + tid];
                    const unsigned long long hh = packf2(hv, hv);
                    a0 = f2fma(hh, packf2(kv.x, kv.y), a0);
                    a1 = f2fma(hh, packf2(kv.z, kv.w), a1);
                }
                float2 e01 = *reinterpret_cast<float2*>(&a0);
                float2 e23 = *reinterpret_cast<float2*>(&a1);
                const int v = len - t0;
                es[t0] = e01.x; lmax = e01.x;
                if (v > 1) { es[t0 + 1] = e01.y; lmax = fmaxf(lmax, e01.y); }
                if (v > 2) { es[t0 + 2] = e23.x; lmax = fmaxf(lmax, e23.x); }
                if (v > 3) { es[t0 + 3] = e23.y; lmax = fmaxf(lmax, e23.y); }
            }
#pragma unroll
            for (int s = 16; s > 0; s >>= 1) lmax = fmaxf(lmax, __shfl_xor_sync(0xffffffffu, lmax, s));
            if (lane == 0) red[wid] = lmax;
            __syncthreads();
            float mx = red[0];
#pragma unroll
            for (int i = 1; i < 16; i++) mx = fmaxf(mx, red[i]);

            float ps = 0.0f;
            if (t0 < len) {
                const int v = (len - t0 < 4) ? (len - t0) : 4;
                for (int i = 0; i < v; i++) {
                    float e = __expf(es[t0 + i] - mx);
                    es[t0 + i] = e;
                    ps += e;
                }
            }
#pragma unroll
            for (int s = 16; s > 0; s >>= 1) ps += __shfl_xor_sync(0xffffffffu, ps, s);
            __syncthreads();                 // everyone done reading red[] for mx
            if (lane == 0) red[wid] = ps;
            __syncthreads();
            float tot = red[0];
#pragma unroll
            for (int i = 1; i < 16; i++) tot += red[i];
            const float inv = 1.0f / tot;

            // ctx: warp per d (d = wid, wid+16, ...), lanes stride over t (coalesced)
            {
                const float4* vT = reinterpret_cast<const float4*>(g_valT + (size_t)n * KD * T_T);
                const float4* es4 = reinterpret_cast<const float4*>(es);
                const int nt4 = (len + 3) >> 2;   // es zero beyond len -> garbage*0 safe
                for (int d = wid; d < 128; d += 16) {
                    unsigned long long a0 = 0ull, a1 = 0ull;
                    for (int tq = lane; tq < nt4; tq += 32) {
                        const float4 vv = vT[(size_t)d * T4 + tq];
                        const float4 aa = es4[tq];
                        a0 = f2fma(packf2(vv.x, vv.y), packf2(aa.x, aa.y), a0);
                        a1 = f2fma(packf2(vv.z, vv.w), packf2(aa.z, aa.w), a1);
                    }
                    float2 f0 = *reinterpret_cast<float2*>(&a0);
                    float2 f1 = *reinterpret_cast<float2*>(&a1);
                    float sum = f0.x + f0.y + f1.x + f1.y;
#pragma unroll
                    for (int s = 16; s > 0; s >>= 1) sum += __shfl_xor_sync(0xffffffffu, sum, s);
                    if (lane == 0) {
                        const float cx = sum * inv;
                        ctxs[d] = cx;
                        g_x1[nxt][d * 64 + n] = cx;   // ctx -> next-step gates1
                    }
                }
            }
            __syncthreads();

            // logits: pred[v] = [h2, ctx] . emb[v] + bout[v]
            {
                const float4 h0 = *reinterpret_cast<const float4*>(&h2s[lane * 4]);
                const float4 c0 = *reinterpret_cast<const float4*>(&ctxs[lane * 4]);
                for (int v = wid; v < V_V; v += 16) {
                    const float4* er = reinterpret_cast<const float4*>(emb + (size_t)v * E_E);
                    const float4 e0 = er[lane], e1 = er[lane + 32];
                    float d = e0.x * h0.x + e0.y * h0.y + e0.z * h0.z + e0.w * h0.w
                            + e1.x * c0.x + e1.y * c0.y + e1.z * c0.z + e1.w * c0.w;
#pragma unroll
                    for (int s = 16; s > 0; s >>= 1) d += __shfl_xor_sync(0xffffffffu, d, s);
                    if (lane == 0) out[((size_t)n * L_L + step) * V_V + v] = d + bout[v];
                }
            }
        }
        gridbar();
    }
}

extern "C" void kernel_launch(void* const* d_in, const int* in_sizes, int n_in,
                              void* d_out, int out_size) {
    mega<<<NBLK, NTHR>>>(
        (const float*)d_in[0], (const float*)d_in[1], (const int*)d_in[2],
        (const int*)d_in[3], (const float*)d_in[4], (const float*)d_in[5],
        (const float*)d_in[6], (const float*)d_in[7], (const float*)d_in[8],
        (const float*)d_in[9], (const float*)d_in[10], (const float*)d_in[11],
        (const float*)d_in[12], (const float*)d_in[13], (float*)d_out);
}

// round 8
// speedup vs baseline: 1.4574x; 1.4574x over previous
#include <cuda_runtime.h>
#include <cstdint>
#include <cstddef>

// Problem: V=35, E=256, H=512, K=128, VS=128, N=64, T=2000, L=300, START=33
#define NBLK 128
#define NTHR 512

#define N_B   64
#define T_T   2000
#define T4    500
#define L_L   300
#define E_E   256
#define H_H   512
#define KD    128
#define V_V   35
#define K2    640
#define START_TOK 33

// ---------------- device scratch (static: no allocation) ----------------
__device__ __align__(16) float g_keyT[(size_t)N_B * KD * T_T];   // [n][d][t]
__device__ __align__(16) float g_valT[(size_t)N_B * KD * T_T];   // [n][d][t]
__device__ __align__(16) float g_W1c[128 * H_H * 4];             // ctx part  [(k*512+j)*4+g]
__device__ __align__(16) float g_W1h[512 * H_H * 4];             // h1 part   [(k*512+j)*4+g]
__device__ __align__(16) float g_W2q[K2 * KD * 4];               // [(k*128+j)*4+g]
__device__ __align__(16) float g_embW1[V_V * H_H * 4];           // [(tok*512+j)*4+g]
__device__ __align__(16) float g_b2[KD * 4];
__device__ __align__(16) float g_pre1[H_H * 4 * N_B];            // [(j*4+g)*64+n] = W_h1 @ h1_prev
__device__ __align__(16) float g_x1[2][128 * N_B];               // ctx only now: [buf][k][n]
__device__ __align__(16) float g_h1[H_H * N_B];                  // h1 [j][n] (single buffer, read in C, written in A)
__device__ __align__(16) float g_x2[2][K2 * N_B];                // [buf][k][n] k<512 h1, k>=512 h2
__device__ __align__(16) float g_c1[H_H * N_B];
__device__ __align__(16) float g_c2[KD * N_B];

__device__ unsigned g_bar_cnt;
__device__ volatile unsigned g_bar_gen;

__device__ __forceinline__ float sigf(float x) { return 1.0f / (1.0f + __expf(-x)); }

__device__ __forceinline__ unsigned long long packf2(float a, float b) {
    float2 f = make_float2(a, b);
    return *reinterpret_cast<unsigned long long*>(&f);
}
__device__ __forceinline__ unsigned long long f2fma(unsigned long long a,
                                                    unsigned long long b,
                                                    unsigned long long c) {
    unsigned long long d;
    asm("fma.rn.f32x2 %0, %1, %2, %3;" : "=l"(d) : "l"(a), "l"(b), "l"(c));
    return d;
}

__device__ __forceinline__ void gridbar() {
    __syncthreads();
    __threadfence();
    if (threadIdx.x == 0) {
        unsigned gen = g_bar_gen;
        if (atomicAdd(&g_bar_cnt, 1u) == NBLK - 1) {
            g_bar_cnt = 0;
            __threadfence();
            g_bar_gen = gen + 1;
        } else {
            while (g_bar_gen == gen) { __nanosleep(64); }
        }
    }
    __syncthreads();
    __threadfence();
}

__global__ __launch_bounds__(NTHR, 1) void mega(
    const float* __restrict__ key, const float* __restrict__ values,
    const int* __restrict__ lens, const int* __restrict__ text,
    const float* __restrict__ emb,
    const float* __restrict__ Wih1, const float* __restrict__ Whh1,
    const float* __restrict__ bih1, const float* __restrict__ bhh1,
    const float* __restrict__ Wih2, const float* __restrict__ Whh2,
    const float* __restrict__ bih2, const float* __restrict__ bhh2,
    const float* __restrict__ bout, float* __restrict__ out)
{
    __shared__ __align__(16) float cb[32 * 4 * 64];     // 32 KB combine / transpose tile
    __shared__ __align__(16) float gsum[4 * 64];
    __shared__ __align__(16) float es[2048];            // softmax weights
    __shared__ __align__(16) float h2s[128];
    __shared__ __align__(16) float ctxs[128];
    __shared__ float red[32];

    const int tid = threadIdx.x;
    const int b = blockIdx.x;
    const int wid = tid >> 5, lane = tid & 31;

    // ======================= PREP =======================
    for (int i = b * NTHR + tid; i < 2 * 128 * N_B; i += NBLK * NTHR) ((float*)g_x1)[i] = 0.0f;
    for (int i = b * NTHR + tid; i < H_H * N_B; i += NBLK * NTHR) g_h1[i] = 0.0f;
    for (int i = b * NTHR + tid; i < 2 * K2 * N_B; i += NBLK * NTHR) ((float*)g_x2)[i] = 0.0f;
    for (int i = b * NTHR + tid; i < H_H * N_B; i += NBLK * NTHR) g_c1[i] = 0.0f;
    for (int i = b * NTHR + tid; i < KD * N_B; i += NBLK * NTHR) g_c2[i] = 0.0f;
    for (int i = b * NTHR + tid; i < H_H * 4 * N_B; i += NBLK * NTHR) g_pre1[i] = 0.0f;

    // W1c: ctx columns (Wih1[:, 256+k]), W1h: Whh1
    for (int idx = b * NTHR + tid; idx < 128 * H_H; idx += NBLK * NTHR) {
        int k = idx / H_H, j = idx % H_H;
        float4 w;
        float* wp = reinterpret_cast<float*>(&w);
#pragma unroll
        for (int g = 0; g < 4; g++) wp[g] = Wih1[(size_t)(g * H_H + j) * 384 + 256 + k];
        *reinterpret_cast<float4*>(&g_W1c[(size_t)idx * 4]) = w;
    }
    for (int idx = b * NTHR + tid; idx < 512 * H_H; idx += NBLK * NTHR) {
        int k = idx / H_H, j = idx % H_H;
        float4 w;
        float* wp = reinterpret_cast<float*>(&w);
#pragma unroll
        for (int g = 0; g < 4; g++) wp[g] = Whh1[(size_t)(g * H_H + j) * 512 + k];
        *reinterpret_cast<float4*>(&g_W1h[(size_t)idx * 4]) = w;
    }
    for (int idx = b * NTHR + tid; idx < K2 * KD; idx += NBLK * NTHR) {
        int k = idx / KD, j = idx % KD;
        float4 w;
        float* wp = reinterpret_cast<float*>(&w);
#pragma unroll
        for (int g = 0; g < 4; g++) {
            int row = g * KD + j;
            wp[g] = (k < 512) ? Wih2[(size_t)row * 512 + k]
                              : Whh2[(size_t)row * 128 + (k - 512)];
        }
        *reinterpret_cast<float4*>(&g_W2q[(size_t)idx * 4]) = w;
    }
    for (int j = b * NTHR + tid; j < KD; j += NBLK * NTHR) {
        float4 w;
        w.x = bih2[j] + bhh2[j];
        w.y = bih2[j + 128] + bhh2[j + 128];
        w.z = bih2[j + 256] + bhh2[j + 256];
        w.w = bih2[j + 384] + bhh2[j + 384];
        *reinterpret_cast<float4*>(&g_b2[j * 4]) = w;
    }
    // embW1
    for (int it = b * 16 + wid; it < V_V * H_H; it += NBLK * 16) {
        int tok = it / H_H, j = it % H_H;
        const float4* e4 = reinterpret_cast<const float4*>(emb + (size_t)tok * E_E);
        float4 ea = e4[lane], eb = e4[lane + 32];
        float a[4];
#pragma unroll
        for (int g = 0; g < 4; g++) {
            const float4* w4 = reinterpret_cast<const float4*>(Wih1 + (size_t)(g * H_H + j) * 384);
            float4 wa = w4[lane], wb = w4[lane + 32];
            a[g] = ea.x * wa.x + ea.y * wa.y + ea.z * wa.z + ea.w * wa.w
                 + eb.x * wb.x + eb.y * wb.y + eb.z * wb.z + eb.w * wb.w;
        }
#pragma unroll
        for (int s = 16; s > 0; s >>= 1) {
#pragma unroll
            for (int g = 0; g < 4; g++) a[g] += __shfl_xor_sync(0xffffffffu, a[g], s);
        }
        if (lane == 0) {
            float4 r;
            r.x = a[0] + bih1[j] + bhh1[j];
            r.y = a[1] + bih1[j + 512] + bhh1[j + 512];
            r.z = a[2] + bih1[j + 1024] + bhh1[j + 1024];
            r.w = a[3] + bih1[j + 1536] + bhh1[j + 1536];
            *reinterpret_cast<float4*>(&g_embW1[(size_t)it * 4]) = r;
        }
    }
    // transpose key/values -> [n][d][t]
    {
        const int tx = tid & 31, ty = tid >> 5;
        for (int tileid = b; tileid < 2 * N_B * 63 * 4; tileid += NBLK) {
            int rem = tileid;
            const float* src = key;
            float* dst = g_keyT;
            if (rem >= N_B * 63 * 4) { rem -= N_B * 63 * 4; src = values; dst = g_valT; }
            int n = rem / (63 * 4);
            int r2 = rem % (63 * 4);
            int t0 = (r2 / 4) * 32, d0 = (r2 % 4) * 32;
            __syncthreads();
#pragma unroll
            for (int r = 0; r < 32; r += 16) {
                int t = t0 + r + ty;
                cb[(r + ty) * 33 + tx] =
                    (t < T_T) ? src[((size_t)n * T_T + t) * KD + d0 + tx] : 0.0f;
            }
            __syncthreads();
#pragma unroll
            for (int r = 0; r < 32; r += 16) {
                int t = t0 + tx;
                if (t < T_T)
                    dst[((size_t)n * KD + d0 + r + ty) * T_T + t] = cb[tx * 33 + (r + ty)];
            }
        }
        __syncthreads();
    }

    gridbar();

    // ======================= MAIN LOOP =======================
    for (int step = 0; step < L_L; step++) {
        const int cur = step & 1, nxt = cur ^ 1;

        // ---- Phase A: gates1 = embW1 + W1c@ctx (K=128) + pre1; cell1. 128 blk x 4 j ----
        {
            const int ks = tid >> 6;        // 0..7 (16 k each)
            const int jl = (tid >> 4) & 3;  // 0..3
            const int nq = tid & 15;        // 0..15
            const int j = b * 4 + jl;
            const float* __restrict__ x = g_x1[cur];
            unsigned long long acc[8];
#pragma unroll
            for (int i = 0; i < 8; i++) acc[i] = 0ull;
#pragma unroll
            for (int i = 0; i < 16; i++) {
                const int k = ks * 16 + i;
                const float4 w4 = *reinterpret_cast<const float4*>(&g_W1c[((size_t)k * 512 + j) * 4]);
                const float4 xv = *reinterpret_cast<const float4*>(&x[k * 64 + nq * 4]);
                const unsigned long long xlo = packf2(xv.x, xv.y);
                const unsigned long long xhi = packf2(xv.z, xv.w);
                acc[0] = f2fma(packf2(w4.x, w4.x), xlo, acc[0]);
                acc[1] = f2fma(packf2(w4.x, w4.x), xhi, acc[1]);
                acc[2] = f2fma(packf2(w4.y, w4.y), xlo, acc[2]);
                acc[3] = f2fma(packf2(w4.y, w4.y), xhi, acc[3]);
                acc[4] = f2fma(packf2(w4.z, w4.z), xlo, acc[4]);
                acc[5] = f2fma(packf2(w4.z, w4.z), xhi, acc[5]);
                acc[6] = f2fma(packf2(w4.w, w4.w), xlo, acc[6]);
                acc[7] = f2fma(packf2(w4.w, w4.w), xhi, acc[7]);
            }
#pragma unroll
            for (int g = 0; g < 4; g++) {
                float2 lo = *reinterpret_cast<float2*>(&acc[g * 2]);
                float2 hi = *reinterpret_cast<float2*>(&acc[g * 2 + 1]);
                *reinterpret_cast<float4*>(&cb[((ks * 4 + jl) * 4 + g) * 64 + nq * 4]) =
                    make_float4(lo.x, lo.y, hi.x, hi.y);
            }
            __syncthreads();
            if (tid < 256) {
                const int jl2 = tid >> 6, n = tid & 63;
                const int j2 = b * 4 + jl2;
                const int tok = (step == 0) ? START_TOK : text[n * L_L + step - 1];
                const float4 g0 = *reinterpret_cast<const float4*>(&g_embW1[((size_t)tok * 512 + j2) * 4]);
                float gi = g0.x + g_pre1[(j2 * 4 + 0) * 64 + n];
                float gf = g0.y + g_pre1[(j2 * 4 + 1) * 64 + n];
                float gg = g0.z + g_pre1[(j2 * 4 + 2) * 64 + n];
                float go = g0.w + g_pre1[(j2 * 4 + 3) * 64 + n];
#pragma unroll
                for (int s = 0; s < 8; s++) {
                    gi += cb[((s * 4 + jl2) * 4 + 0) * 64 + n];
                    gf += cb[((s * 4 + jl2) * 4 + 1) * 64 + n];
                    gg += cb[((s * 4 + jl2) * 4 + 2) * 64 + n];
                    go += cb[((s * 4 + jl2) * 4 + 3) * 64 + n];
                }
                float c = g_c1[j2 * 64 + n];
                c = sigf(gf) * c + sigf(gi) * tanhf(gg);
                float h = sigf(go) * tanhf(c);
                g_c1[j2 * 64 + n] = c;
                g_h1[j2 * 64 + n] = h;               // for pre1 GEMM (phase C)
                g_x2[cur][j2 * 64 + n] = h;          // this-step gates2
            }
        }
        gridbar();

        // ---- Phase B: gates2 (K=640) + cell2; 128 blocks, 1 j each ----
        {
            const int j = b;
            const int ks = tid >> 4;        // 0..31 (20 k each)
            const int nq = tid & 15;
            const float* __restrict__ x = g_x2[cur];
            unsigned long long acc[8];
#pragma unroll
            for (int i = 0; i < 8; i++) acc[i] = 0ull;
#pragma unroll 4
            for (int i = 0; i < 20; i++) {
                const int k = ks * 20 + i;
                const float4 w4 = *reinterpret_cast<const float4*>(&g_W2q[((size_t)k * 128 + j) * 4]);
                const float4 xv = *reinterpret_cast<const float4*>(&x[k * 64 + nq * 4]);
                const unsigned long long xlo = packf2(xv.x, xv.y);
                const unsigned long long xhi = packf2(xv.z, xv.w);
                acc[0] = f2fma(packf2(w4.x, w4.x), xlo, acc[0]);
                acc[1] = f2fma(packf2(w4.x, w4.x), xhi, acc[1]);
                acc[2] = f2fma(packf2(w4.y, w4.y), xlo, acc[2]);
                acc[3] = f2fma(packf2(w4.y, w4.y), xhi, acc[3]);
                acc[4] = f2fma(packf2(w4.z, w4.z), xlo, acc[4]);
                acc[5] = f2fma(packf2(w4.z, w4.z), xhi, acc[5]);
                acc[6] = f2fma(packf2(w4.w, w4.w), xlo, acc[6]);
                acc[7] = f2fma(packf2(w4.w, w4.w), xhi, acc[7]);
            }
#pragma unroll
            for (int g = 0; g < 4; g++) {
                float2 lo = *reinterpret_cast<float2*>(&acc[g * 2]);
                float2 hi = *reinterpret_cast<float2*>(&acc[g * 2 + 1]);
                *reinterpret_cast<float4*>(&cb[(ks * 4 + g) * 64 + nq * 4]) =
                    make_float4(lo.x, lo.y, hi.x, hi.y);
            }
            __syncthreads();
            if (tid < 256) {
                const int g = tid >> 6, n = tid & 63;
                float s = 0.0f;
#pragma unroll
                for (int ks2 = 0; ks2 < 32; ks2++) s += cb[(ks2 * 4 + g) * 64 + n];
                gsum[g * 64 + n] = s;
            }
            __syncthreads();
            if (tid < 64) {
                const int n = tid;
                const float4 bb = *reinterpret_cast<const float4*>(&g_b2[j * 4]);
                float gi = bb.x + gsum[0 * 64 + n];
                float gf = bb.y + gsum[1 * 64 + n];
                float gg = bb.z + gsum[2 * 64 + n];
                float go = bb.w + gsum[3 * 64 + n];
                float c = g_c2[j * 64 + n];
                c = sigf(gf) * c + sigf(gi) * tanhf(gg);
                float h = sigf(go) * tanhf(c);
                g_c2[j * 64 + n] = c;
                g_x2[nxt][(512 + j) * 64 + n] = h;   // next-step gates2 + this-step attn
            }
        }
        gridbar();

        // ---- Phase C: attention+logits on blocks 0..63; pre1 GEMM on blocks 64..127 ----
        if (b < 64) {
            const int n = b;
            if (tid < 128) h2s[tid] = g_x2[nxt][(512 + tid) * 64 + n];
            __syncthreads();

            const int len = lens[n];
            const int t0 = tid * 4;
            float4* es4w = reinterpret_cast<float4*>(es);

            // energy: thread owns 4 t; 16 loads in flight
            float lmax = -3e38f;
            if (t0 < len) {
                const float4* kT = reinterpret_cast<const float4*>(g_keyT + (size_t)n * KD * T_T);
                unsigned long long a0 = 0ull, a1 = 0ull;
#pragma unroll
                for (int dc = 0; dc < 128; dc += 16) {
                    float4 kv[16];
#pragma unroll
                    for (int i = 0; i < 16; i++) kv[i] = kT[(size_t)(dc + i) * T4 + tid];
#pragma unroll
                    for (int i = 0; i < 16; i++) {
                        const float hv = h2s[dc + i];
                        const unsigned long long hh = packf2(hv, hv);
                        a0 = f2fma(hh, packf2(kv[i].x, kv[i].y), a0);
                        a1 = f2fma(hh, packf2(kv[i].z, kv[i].w), a1);
                    }
                }
                float2 e01 = *reinterpret_cast<float2*>(&a0);
                float2 e23 = *reinterpret_cast<float2*>(&a1);
                es4w[tid] = make_float4(e01.x, e01.y, e23.x, e23.y);
                const int v = len - t0;
                lmax = e01.x;
                if (v > 1) lmax = fmaxf(lmax, e01.y);
                if (v > 2) lmax = fmaxf(lmax, e23.x);
                if (v > 3) lmax = fmaxf(lmax, e23.y);
            }
#pragma unroll
            for (int s = 16; s > 0; s >>= 1) lmax = fmaxf(lmax, __shfl_xor_sync(0xffffffffu, lmax, s));
            if (lane == 0) red[wid] = lmax;
            __syncthreads();
            float mx = red[0];
#pragma unroll
            for (int i = 1; i < 16; i++) mx = fmaxf(mx, red[i]);

            // exp + zero tail + sum
            float ps = 0.0f;
            if (t0 < len) {
                float4 e = es4w[tid];
                const int v = len - t0;
                e.x = __expf(e.x - mx);
                e.y = (v > 1) ? __expf(e.y - mx) : 0.0f;
                e.z = (v > 2) ? __expf(e.z - mx) : 0.0f;
                e.w = (v > 3) ? __expf(e.w - mx) : 0.0f;
                es4w[tid] = e;
                ps = e.x + e.y + e.z + e.w;
            }
#pragma unroll
            for (int s = 16; s > 0; s >>= 1) ps += __shfl_xor_sync(0xffffffffu, ps, s);
            __syncthreads();
            if (lane == 0) red[wid] = ps;
            __syncthreads();
            float tot = red[0];
#pragma unroll
            for (int i = 1; i < 16; i++) tot += red[i];
            const float inv = 1.0f / tot;

            // ctx: 2 d per warp pass, unroll 4 (>=12 loads in flight)
            {
                const float4* vT = reinterpret_cast<const float4*>(g_valT + (size_t)n * KD * T_T);
                const float4* es4 = reinterpret_cast<const float4*>(es);
                const int nt4 = (len + 3) >> 2;
                for (int d = wid * 2; d < 128; d += 32) {
                    unsigned long long a0 = 0ull, a1 = 0ull, b0 = 0ull, b1 = 0ull;
#pragma unroll 4
                    for (int tq = lane; tq < nt4; tq += 32) {
                        const float4 aa = es4[tq];
                        const float4 v0 = vT[(size_t)d * T4 + tq];
                        const float4 v1 = vT[(size_t)(d + 1) * T4 + tq];
                        const unsigned long long alo = packf2(aa.x, aa.y);
                        const unsigned long long ahi = packf2(aa.z, aa.w);
                        a0 = f2fma(packf2(v0.x, v0.y), alo, a0);
                        a1 = f2fma(packf2(v0.z, v0.w), ahi, a1);
                        b0 = f2fma(packf2(v1.x, v1.y), alo, b0);
                        b1 = f2fma(packf2(v1.z, v1.w), ahi, b1);
                    }
                    float2 f0 = *reinterpret_cast<float2*>(&a0);
                    float2 f1 = *reinterpret_cast<float2*>(&a1);
                    float2 f2 = *reinterpret_cast<float2*>(&b0);
                    float2 f3 = *reinterpret_cast<float2*>(&b1);
                    float s0 = f0.x + f0.y + f1.x + f1.y;
                    float s1 = f2.x + f2.y + f3.x + f3.y;
#pragma unroll
                    for (int s = 16; s > 0; s >>= 1) {
                        s0 += __shfl_xor_sync(0xffffffffu, s0, s);
                        s1 += __shfl_xor_sync(0xffffffffu, s1, s);
                    }
                    if (lane == 0) {
                        const float cx0 = s0 * inv, cx1 = s1 * inv;
                        ctxs[d] = cx0; ctxs[d + 1] = cx1;
                        g_x1[nxt][d * 64 + n] = cx0;
                        g_x1[nxt][(d + 1) * 64 + n] = cx1;
                    }
                }
            }
            __syncthreads();

            // logits
            {
                const float4 h0 = *reinterpret_cast<const float4*>(&h2s[lane * 4]);
                const float4 c0 = *reinterpret_cast<const float4*>(&ctxs[lane * 4]);
                for (int v = wid; v < V_V; v += 16) {
                    const float4* er = reinterpret_cast<const float4*>(emb + (size_t)v * E_E);
                    const float4 e0 = er[lane], e1 = er[lane + 32];
                    float d = e0.x * h0.x + e0.y * h0.y + e0.z * h0.z + e0.w * h0.w
                            + e1.x * c0.x + e1.y * c0.y + e1.z * c0.z + e1.w * c0.w;
#pragma unroll
                    for (int s = 16; s > 0; s >>= 1) d += __shfl_xor_sync(0xffffffffu, d, s);
                    if (lane == 0) out[((size_t)n * L_L + step) * V_V + v] = d + bout[v];
                }
            }
        } else {
            // pre1 = W1h @ h1(this step), for gates1 of step+1. 64 blocks x 8 j.
            const int j0 = (b - 64) * 8;
            const int ks = tid >> 7;        // 0..3 (128 k each)
            const int jl = (tid >> 4) & 7;  // 0..7
            const int nq = tid & 15;
            const int j = j0 + jl;
            unsigned long long acc[8];
#pragma unroll
            for (int i = 0; i < 8; i++) acc[i] = 0ull;
#pragma unroll 4
            for (int i = 0; i < 128; i++) {
                const int k = ks * 128 + i;
                const float4 w4 = *reinterpret_cast<const float4*>(&g_W1h[((size_t)k * 512 + j) * 4]);
                const float4 xv = *reinterpret_cast<const float4*>(&g_h1[k * 64 + nq * 4]);
                const unsigned long long xlo = packf2(xv.x, xv.y);
                const unsigned long long xhi = packf2(xv.z, xv.w);
                acc[0] = f2fma(packf2(w4.x, w4.x), xlo, acc[0]);
                acc[1] = f2fma(packf2(w4.x, w4.x), xhi, acc[1]);
                acc[2] = f2fma(packf2(w4.y, w4.y), xlo, acc[2]);
                acc[3] = f2fma(packf2(w4.y, w4.y), xhi, acc[3]);
                acc[4] = f2fma(packf2(w4.z, w4.z), xlo, acc[4]);
                acc[5] = f2fma(packf2(w4.z, w4.z), xhi, acc[5]);
                acc[6] = f2fma(packf2(w4.w, w4.w), xlo, acc[6]);
                acc[7] = f2fma(packf2(w4.w, w4.w), xhi, acc[7]);
            }
#pragma unroll
            for (int g = 0; g < 4; g++) {
                float2 lo = *reinterpret_cast<float2*>(&acc[g * 2]);
                float2 hi = *reinterpret_cast<float2*>(&acc[g * 2 + 1]);
                *reinterpret_cast<float4*>(&cb[((ks * 8 + jl) * 4 + g) * 64 + nq * 4]) =
                    make_float4(lo.x, lo.y, hi.x, hi.y);
            }
            __syncthreads();
            {
                const int jl2 = tid >> 6, n = tid & 63;   // all 512 threads
                const int j2 = j0 + jl2;
#pragma unroll
                for (int g = 0; g < 4; g++) {
                    float s = cb[((0 * 8 + jl2) * 4 + g) * 64 + n]
                            + cb[((1 * 8 + jl2) * 4 + g) * 64 + n]
                            + cb[((2 * 8 + jl2) * 4 + g) * 64 + n]
                            + cb[((3 * 8 + jl2) * 4 + g) * 64 + n];
                    g_pre1[(j2 * 4 + g) * 64 + n] = s;
                }
            }
        }
        gridbar();
    }
}

extern "C" void kernel_launch(void* const* d_in, const int* in_sizes, int n_in,
                              void* d_out, int out_size) {
    mega<<<NBLK, NTHR>>>(
        (const float*)d_in[0], (const float*)d_in[1], (const int*)d_in[2],
        (const int*)d_in[3], (const float*)d_in[4], (const float*)d_in[5],
        (const float*)d_in[6], (const float*)d_in[7], (const float*)d_in[8],
        (const float*)d_in[9], (const float*)d_in[10], (const float*)d_in[11],
        (const float*)d_in[12], (const float*)d_in[13], (float*)d_out);
}

// round 9
// speedup vs baseline: 1.5731x; 1.0794x over previous
#include <cuda_runtime.h>
#include <cstdint>
#include <cstddef>

// Problem: V=35, E=256, H=512, K=128, VS=128, N=64, T=2000, L=300, START=33
#define NBLK 128
#define NTHR 512

#define N_B   64
#define T_T   2000
#define T4    500
#define L_L   300
#define E_E   256
#define H_H   512
#define KD    128
#define V_V   35
#define K2    640
#define START_TOK 33

// ---------------- device scratch (static: no allocation) ----------------
__device__ __align__(16) float g_keyT[(size_t)N_B * KD * T_T];   // [n][d][t]
__device__ __align__(16) float g_valT[(size_t)N_B * KD * T_T];   // [n][d][t]
__device__ __align__(16) float g_W1c[128 * H_H * 4];             // ctx part  [(k*512+j)*4+g]
__device__ __align__(16) float g_W1h[512 * H_H * 4];             // h1 part   [(k*512+j)*4+g]
__device__ __align__(16) float g_W2q[K2 * KD * 4];               // [(k*128+j)*4+g]
__device__ __align__(16) float g_embW1[V_V * H_H * 4];           // [(tok*512+j)*4+g]
__device__ __align__(16) float g_b2[KD * 4];
__device__ __align__(16) float g_pre1[H_H * 4 * N_B];            // [(j*4+g)*64+n]
__device__ __align__(16) float g_x1[2][128 * N_B];               // ctx [buf][k][n]
__device__ __align__(16) float g_h1[H_H * N_B];                  // h1 [j][n]
__device__ __align__(16) float g_x2[2][K2 * N_B];                // [buf][k][n] k<512 h1, k>=512 h2
__device__ __align__(16) float g_c1[H_H * N_B];
__device__ __align__(16) float g_c2[KD * N_B];

__device__ unsigned g_arrive[NBLK * 32];   // one slot per block, 128B padded
__device__ unsigned g_release;

__device__ __forceinline__ float sigf(float x) { return 1.0f / (1.0f + __expf(-x)); }

__device__ __forceinline__ unsigned long long packf2(float a, float b) {
    float2 f = make_float2(a, b);
    return *reinterpret_cast<unsigned long long*>(&f);
}
__device__ __forceinline__ unsigned long long f2fma(unsigned long long a,
                                                    unsigned long long b,
                                                    unsigned long long c) {
    unsigned long long d;
    asm("fma.rn.f32x2 %0, %1, %2, %3;" : "=l"(d) : "l"(a), "l"(b), "l"(c));
    return d;
}

// ---------------- replay-safe fence-free grid barrier ----------------
struct Bar { unsigned gen, s0, r0, sb0, sb1, sb2, sb3; };

__device__ __forceinline__ unsigned ld_rlx(const unsigned* p) {
    unsigned v; asm volatile("ld.relaxed.gpu.u32 %0, [%1];" : "=r"(v) : "l"(p)); return v;
}
__device__ __forceinline__ unsigned ld_acq(const unsigned* p) {
    unsigned v; asm volatile("ld.acquire.gpu.u32 %0, [%1];" : "=r"(v) : "l"(p) : "memory"); return v;
}
__device__ __forceinline__ void st_rel(unsigned* p, unsigned v) {
    asm volatile("st.release.gpu.u32 [%0], %1;" :: "l"(p), "r"(v) : "memory");
}

__device__ __forceinline__ void gridbar(Bar& bs) {
    bs.gen++;
    __syncthreads();
    if (threadIdx.x == 0) st_rel(&g_arrive[blockIdx.x * 32], bs.s0 + bs.gen);
    if (blockIdx.x == 0) {
        if (threadIdx.x < 32) {
            unsigned base[4] = {bs.sb0, bs.sb1, bs.sb2, bs.sb3};
#pragma unroll
            for (int i = 0; i < 4; i++) {
                const unsigned tgt = base[i] + bs.gen;
                while (ld_acq(&g_arrive[(threadIdx.x + 32 * i) * 32]) != tgt) {}
            }
            __syncwarp();
            if (threadIdx.x == 0) st_rel(&g_release, bs.r0 + bs.gen);
        }
    } else {
        if (threadIdx.x == 0) {
            const unsigned tgt = bs.r0 + bs.gen;
            while (ld_acq(&g_release) != tgt) {}
        }
    }
    __syncthreads();
}

__global__ __launch_bounds__(NTHR, 1) void mega(
    const float* __restrict__ key, const float* __restrict__ values,
    const int* __restrict__ lens, const int* __restrict__ text,
    const float* __restrict__ emb,
    const float* __restrict__ Wih1, const float* __restrict__ Whh1,
    const float* __restrict__ bih1, const float* __restrict__ bhh1,
    const float* __restrict__ Wih2, const float* __restrict__ Whh2,
    const float* __restrict__ bih2, const float* __restrict__ bhh2,
    const float* __restrict__ bout, float* __restrict__ out)
{
    __shared__ __align__(16) float cb[32 * 4 * 64];     // 32 KB combine / transpose tile
    __shared__ __align__(16) float gsum[4 * 64];
    __shared__ __align__(16) float es[2048];
    __shared__ __align__(16) float h2s[128];
    __shared__ __align__(16) float ctxs[128];
    __shared__ float red[32];

    const int tid = threadIdx.x;
    const int b = blockIdx.x;
    const int wid = tid >> 5, lane = tid & 31;

    // barrier bases (quiescent values from any previous launch)
    Bar bs; bs.gen = 0; bs.s0 = 0; bs.r0 = 0; bs.sb0 = bs.sb1 = bs.sb2 = bs.sb3 = 0;
    if (tid == 0) { bs.s0 = ld_rlx(&g_arrive[b * 32]); bs.r0 = ld_rlx(&g_release); }
    if (b == 0 && tid < 32) {
        bs.sb0 = ld_rlx(&g_arrive[(tid +  0) * 32]);
        bs.sb1 = ld_rlx(&g_arrive[(tid + 32) * 32]);
        bs.sb2 = ld_rlx(&g_arrive[(tid + 64) * 32]);
        bs.sb3 = ld_rlx(&g_arrive[(tid + 96) * 32]);
    }

    // ======================= PREP =======================
    for (int i = b * NTHR + tid; i < 2 * 128 * N_B; i += NBLK * NTHR) ((float*)g_x1)[i] = 0.0f;
    for (int i = b * NTHR + tid; i < H_H * N_B; i += NBLK * NTHR) g_h1[i] = 0.0f;
    for (int i = b * NTHR + tid; i < 2 * K2 * N_B; i += NBLK * NTHR) ((float*)g_x2)[i] = 0.0f;
    for (int i = b * NTHR + tid; i < H_H * N_B; i += NBLK * NTHR) g_c1[i] = 0.0f;
    for (int i = b * NTHR + tid; i < KD * N_B; i += NBLK * NTHR) g_c2[i] = 0.0f;
    for (int i = b * NTHR + tid; i < H_H * 4 * N_B; i += NBLK * NTHR) g_pre1[i] = 0.0f;

    for (int idx = b * NTHR + tid; idx < 128 * H_H; idx += NBLK * NTHR) {
        int k = idx / H_H, j = idx % H_H;
        float4 w;
        float* wp = reinterpret_cast<float*>(&w);
#pragma unroll
        for (int g = 0; g < 4; g++) wp[g] = Wih1[(size_t)(g * H_H + j) * 384 + 256 + k];
        *reinterpret_cast<float4*>(&g_W1c[(size_t)idx * 4]) = w;
    }
    for (int idx = b * NTHR + tid; idx < 512 * H_H; idx += NBLK * NTHR) {
        int k = idx / H_H, j = idx % H_H;
        float4 w;
        float* wp = reinterpret_cast<float*>(&w);
#pragma unroll
        for (int g = 0; g < 4; g++) wp[g] = Whh1[(size_t)(g * H_H + j) * 512 + k];
        *reinterpret_cast<float4*>(&g_W1h[(size_t)idx * 4]) = w;
    }
    for (int idx = b * NTHR + tid; idx < K2 * KD; idx += NBLK * NTHR) {
        int k = idx / KD, j = idx % KD;
        float4 w;
        float* wp = reinterpret_cast<float*>(&w);
#pragma unroll
        for (int g = 0; g < 4; g++) {
            int row = g * KD + j;
            wp[g] = (k < 512) ? Wih2[(size_t)row * 512 + k]
                              : Whh2[(size_t)row * 128 + (k - 512)];
        }
        *reinterpret_cast<float4*>(&g_W2q[(size_t)idx * 4]) = w;
    }
    for (int j = b * NTHR + tid; j < KD; j += NBLK * NTHR) {
        float4 w;
        w.x = bih2[j] + bhh2[j];
        w.y = bih2[j + 128] + bhh2[j + 128];
        w.z = bih2[j + 256] + bhh2[j + 256];
        w.w = bih2[j + 384] + bhh2[j + 384];
        *reinterpret_cast<float4*>(&g_b2[j * 4]) = w;
    }
    for (int it = b * 16 + wid; it < V_V * H_H; it += NBLK * 16) {
        int tok = it / H_H, j = it % H_H;
        const float4* e4 = reinterpret_cast<const float4*>(emb + (size_t)tok * E_E);
        float4 ea = e4[lane], eb = e4[lane + 32];
        float a[4];
#pragma unroll
        for (int g = 0; g < 4; g++) {
            const float4* w4 = reinterpret_cast<const float4*>(Wih1 + (size_t)(g * H_H + j) * 384);
            float4 wa = w4[lane], wb = w4[lane + 32];
            a[g] = ea.x * wa.x + ea.y * wa.y + ea.z * wa.z + ea.w * wa.w
                 + eb.x * wb.x + eb.y * wb.y + eb.z * wb.z + eb.w * wb.w;
        }
#pragma unroll
        for (int s = 16; s > 0; s >>= 1) {
#pragma unroll
            for (int g = 0; g < 4; g++) a[g] += __shfl_xor_sync(0xffffffffu, a[g], s);
        }
        if (lane == 0) {
            float4 r;
            r.x = a[0] + bih1[j] + bhh1[j];
            r.y = a[1] + bih1[j + 512] + bhh1[j + 512];
            r.z = a[2] + bih1[j + 1024] + bhh1[j + 1024];
            r.w = a[3] + bih1[j + 1536] + bhh1[j + 1536];
            *reinterpret_cast<float4*>(&g_embW1[(size_t)it * 4]) = r;
        }
    }
    // transpose key/values -> [n][d][t]  (252 tiles per block, uniform)
    {
        const int tx = tid & 31, ty = tid >> 5;
        for (int tileid = b; tileid < 2 * N_B * 63 * 4; tileid += NBLK) {
            int rem = tileid;
            const float* src = key;
            float* dst = g_keyT;
            if (rem >= N_B * 63 * 4) { rem -= N_B * 63 * 4; src = values; dst = g_valT; }
            int n = rem / (63 * 4);
            int r2 = rem % (63 * 4);
            int t0 = (r2 / 4) * 32, d0 = (r2 % 4) * 32;
            __syncthreads();
#pragma unroll
            for (int r = 0; r < 32; r += 16) {
                int t = t0 + r + ty;
                cb[(r + ty) * 33 + tx] =
                    (t < T_T) ? src[((size_t)n * T_T + t) * KD + d0 + tx] : 0.0f;
            }
            __syncthreads();
#pragma unroll
            for (int r = 0; r < 32; r += 16) {
                int t = t0 + tx;
                if (t < T_T)
                    dst[((size_t)n * KD + d0 + r + ty) * T_T + t] = cb[tx * 33 + (r + ty)];
            }
        }
        __syncthreads();
    }

    gridbar(bs);

    // ======================= MAIN LOOP =======================
    for (int step = 0; step < L_L; step++) {
        const int cur = step & 1, nxt = cur ^ 1;

        // ---- Phase A: gates1 = embW1 + W1c@ctx (K=128) + pre1; cell1 ----
        {
            const int ks = tid >> 6;        // 0..7 (16 k each)
            const int jl = (tid >> 4) & 3;  // 0..3
            const int nq = tid & 15;        // 0..15
            const int j = b * 4 + jl;
            const float4* __restrict__ x4 = reinterpret_cast<const float4*>(g_x1[cur]);
            unsigned long long acc[8];
#pragma unroll
            for (int i = 0; i < 8; i++) acc[i] = 0ull;
#pragma unroll
            for (int kc = 0; kc < 16; kc += 8) {
                float4 xv[8];
#pragma unroll
                for (int i = 0; i < 8; i++)
                    xv[i] = __ldcg(&x4[(ks * 16 + kc + i) * 16 + nq]);
#pragma unroll
                for (int i = 0; i < 8; i++) {
                    const int k = ks * 16 + kc + i;
                    const float4 w4 = *reinterpret_cast<const float4*>(&g_W1c[((size_t)k * 512 + j) * 4]);
                    const unsigned long long xlo = packf2(xv[i].x, xv[i].y);
                    const unsigned long long xhi = packf2(xv[i].z, xv[i].w);
                    acc[0] = f2fma(packf2(w4.x, w4.x), xlo, acc[0]);
                    acc[1] = f2fma(packf2(w4.x, w4.x), xhi, acc[1]);
                    acc[2] = f2fma(packf2(w4.y, w4.y), xlo, acc[2]);
                    acc[3] = f2fma(packf2(w4.y, w4.y), xhi, acc[3]);
                    acc[4] = f2fma(packf2(w4.z, w4.z), xlo, acc[4]);
                    acc[5] = f2fma(packf2(w4.z, w4.z), xhi, acc[5]);
                    acc[6] = f2fma(packf2(w4.w, w4.w), xlo, acc[6]);
                    acc[7] = f2fma(packf2(w4.w, w4.w), xhi, acc[7]);
                }
            }
#pragma unroll
            for (int g = 0; g < 4; g++) {
                float2 lo = *reinterpret_cast<float2*>(&acc[g * 2]);
                float2 hi = *reinterpret_cast<float2*>(&acc[g * 2 + 1]);
                *reinterpret_cast<float4*>(&cb[((ks * 4 + jl) * 4 + g) * 64 + nq * 4]) =
                    make_float4(lo.x, lo.y, hi.x, hi.y);
            }
            __syncthreads();
            if (tid < 256) {
                const int jl2 = tid >> 6, n = tid & 63;
                const int j2 = b * 4 + jl2;
                const int tok = (step == 0) ? START_TOK : text[n * L_L + step - 1];
                const float4 g0 = *reinterpret_cast<const float4*>(&g_embW1[((size_t)tok * 512 + j2) * 4]);
                float gi = g0.x + __ldcg(&g_pre1[(j2 * 4 + 0) * 64 + n]);
                float gf = g0.y + __ldcg(&g_pre1[(j2 * 4 + 1) * 64 + n]);
                float gg = g0.z + __ldcg(&g_pre1[(j2 * 4 + 2) * 64 + n]);
                float go = g0.w + __ldcg(&g_pre1[(j2 * 4 + 3) * 64 + n]);
#pragma unroll
                for (int s = 0; s < 8; s++) {
                    gi += cb[((s * 4 + jl2) * 4 + 0) * 64 + n];
                    gf += cb[((s * 4 + jl2) * 4 + 1) * 64 + n];
                    gg += cb[((s * 4 + jl2) * 4 + 2) * 64 + n];
                    go += cb[((s * 4 + jl2) * 4 + 3) * 64 + n];
                }
                float c = g_c1[j2 * 64 + n];
                c = sigf(gf) * c + sigf(gi) * tanhf(gg);
                float h = sigf(go) * tanhf(c);
                g_c1[j2 * 64 + n] = c;              // block-private
                __stcg(&g_h1[j2 * 64 + n], h);      // for pre1 (phase C)
                __stcg(&g_x2[cur][j2 * 64 + n], h); // this-step gates2
            }
        }
        gridbar(bs);

        // ---- Phase B: gates2 (K=640) + cell2; 128 blocks, 1 j each ----
        {
            const int j = b;
            const int ks = tid >> 4;        // 0..31 (20 k each)
            const int nq = tid & 15;
            const float4* __restrict__ x4 = reinterpret_cast<const float4*>(g_x2[cur]);
            unsigned long long acc[8];
#pragma unroll
            for (int i = 0; i < 8; i++) acc[i] = 0ull;
#pragma unroll
            for (int kc = 0; kc < 20; kc += 10) {
                float4 xv[10];
#pragma unroll
                for (int i = 0; i < 10; i++)
                    xv[i] = __ldcg(&x4[(ks * 20 + kc + i) * 16 + nq]);
#pragma unroll
                for (int i = 0; i < 10; i++) {
                    const int k = ks * 20 + kc + i;
                    const float4 w4 = *reinterpret_cast<const float4*>(&g_W2q[((size_t)k * 128 + j) * 4]);
                    const unsigned long long xlo = packf2(xv[i].x, xv[i].y);
                    const unsigned long long xhi = packf2(xv[i].z, xv[i].w);
                    acc[0] = f2fma(packf2(w4.x, w4.x), xlo, acc[0]);
                    acc[1] = f2fma(packf2(w4.x, w4.x), xhi, acc[1]);
                    acc[2] = f2fma(packf2(w4.y, w4.y), xlo, acc[2]);
                    acc[3] = f2fma(packf2(w4.y, w4.y), xhi, acc[3]);
                    acc[4] = f2fma(packf2(w4.z, w4.z), xlo, acc[4]);
                    acc[5] = f2fma(packf2(w4.z, w4.z), xhi, acc[5]);
                    acc[6] = f2fma(packf2(w4.w, w4.w), xlo, acc[6]);
                    acc[7] = f2fma(packf2(w4.w, w4.w), xhi, acc[7]);
                }
            }
#pragma unroll
            for (int g = 0; g < 4; g++) {
                float2 lo = *reinterpret_cast<float2*>(&acc[g * 2]);
                float2 hi = *reinterpret_cast<float2*>(&acc[g * 2 + 1]);
                *reinterpret_cast<float4*>(&cb[(ks * 4 + g) * 64 + nq * 4]) =
                    make_float4(lo.x, lo.y, hi.x, hi.y);
            }
            __syncthreads();
            if (tid < 256) {
                const int g = tid >> 6, n = tid & 63;
                float s = 0.0f;
#pragma unroll
                for (int ks2 = 0; ks2 < 32; ks2++) s += cb[(ks2 * 4 + g) * 64 + n];
                gsum[g * 64 + n] = s;
            }
            __syncthreads();
            if (tid < 64) {
                const int n = tid;
                const float4 bb = *reinterpret_cast<const float4*>(&g_b2[j * 4]);
                float gi = bb.x + gsum[0 * 64 + n];
                float gf = bb.y + gsum[1 * 64 + n];
                float gg = bb.z + gsum[2 * 64 + n];
                float go = bb.w + gsum[3 * 64 + n];
                float c = g_c2[j * 64 + n];
                c = sigf(gf) * c + sigf(gi) * tanhf(gg);
                float h = sigf(go) * tanhf(c);
                g_c2[j * 64 + n] = c;               // block-private
                __stcg(&g_x2[nxt][(512 + j) * 64 + n], h);
            }
        }
        gridbar(bs);

        // ---- Phase C: attention+logits (blocks 0..63) || pre1 GEMM (64..127) ----
        if (b < 64) {
            const int n = b;
            if (tid < 128) h2s[tid] = __ldcg(&g_x2[nxt][(512 + tid) * 64 + n]);
            __syncthreads();

            const int len = lens[n];
            const int t0 = tid * 4;
            float4* es4w = reinterpret_cast<float4*>(es);

            float lmax = -3e38f;
            if (t0 < len) {
                const float4* kT = reinterpret_cast<const float4*>(g_keyT + (size_t)n * KD * T_T);
                unsigned long long a0 = 0ull, a1 = 0ull;
#pragma unroll
                for (int dc = 0; dc < 128; dc += 16) {
                    float4 kv[16];
#pragma unroll
                    for (int i = 0; i < 16; i++) kv[i] = __ldcg(&kT[(size_t)(dc + i) * T4 + tid]);
#pragma unroll
                    for (int i = 0; i < 16; i++) {
                        const float hv = h2s[dc + i];
                        const unsigned long long hh = packf2(hv, hv);
                        a0 = f2fma(hh, packf2(kv[i].x, kv[i].y), a0);
                        a1 = f2fma(hh, packf2(kv[i].z, kv[i].w), a1);
                    }
                }
                float2 e01 = *reinterpret_cast<float2*>(&a0);
                float2 e23 = *reinterpret_cast<float2*>(&a1);
                es4w[tid] = make_float4(e01.x, e01.y, e23.x, e23.y);
                const int v = len - t0;
                lmax = e01.x;
                if (v > 1) lmax = fmaxf(lmax, e01.y);
                if (v > 2) lmax = fmaxf(lmax, e23.x);
                if (v > 3) lmax = fmaxf(lmax, e23.y);
            }
#pragma unroll
            for (int s = 16; s > 0; s >>= 1) lmax = fmaxf(lmax, __shfl_xor_sync(0xffffffffu, lmax, s));
            if (lane == 0) red[wid] = lmax;
            __syncthreads();
            float mx = red[0];
#pragma unroll
            for (int i = 1; i < 16; i++) mx = fmaxf(mx, red[i]);

            float ps = 0.0f;
            if (t0 < len) {
                float4 e = es4w[tid];
                const int v = len - t0;
                e.x = __expf(e.x - mx);
                e.y = (v > 1) ? __expf(e.y - mx) : 0.0f;
                e.z = (v > 2) ? __expf(e.z - mx) : 0.0f;
                e.w = (v > 3) ? __expf(e.w - mx) : 0.0f;
                es4w[tid] = e;
                ps = e.x + e.y + e.z + e.w;
            }
#pragma unroll
            for (int s = 16; s > 0; s >>= 1) ps += __shfl_xor_sync(0xffffffffu, ps, s);
            __syncthreads();
            if (lane == 0) red[wid] = ps;
            __syncthreads();
            float tot = red[0];
#pragma unroll
            for (int i = 1; i < 16; i++) tot += red[i];
            const float inv = 1.0f / tot;

            {
                const float4* vT = reinterpret_cast<const float4*>(g_valT + (size_t)n * KD * T_T);
                const float4* es4 = reinterpret_cast<const float4*>(es);
                const int nt4 = (len + 3) >> 2;
                for (int d = wid * 2; d < 128; d += 32) {
                    unsigned long long a0 = 0ull, a1 = 0ull, b0 = 0ull, b1 = 0ull;
#pragma unroll 4
                    for (int tq = lane; tq < nt4; tq += 32) {
                        const float4 aa = es4[tq];
                        const float4 v0 = __ldcg(&vT[(size_t)d * T4 + tq]);
                        const float4 v1 = __ldcg(&vT[(size_t)(d + 1) * T4 + tq]);
                        const unsigned long long alo = packf2(aa.x, aa.y);
                        const unsigned long long ahi = packf2(aa.z, aa.w);
                        a0 = f2fma(packf2(v0.x, v0.y), alo, a0);
                        a1 = f2fma(packf2(v0.z, v0.w), ahi, a1);
                        b0 = f2fma(packf2(v1.x, v1.y), alo, b0);
                        b1 = f2fma(packf2(v1.z, v1.w), ahi, b1);
                    }
                    float2 f0 = *reinterpret_cast<float2*>(&a0);
                    float2 f1 = *reinterpret_cast<float2*>(&a1);
                    float2 f2 = *reinterpret_cast<float2*>(&b0);
                    float2 f3 = *reinterpret_cast<float2*>(&b1);
                    float s0 = f0.x + f0.y + f1.x + f1.y;
                    float s1 = f2.x + f2.y + f3.x + f3.y;
#pragma unroll
                    for (int s = 16; s > 0; s >>= 1) {
                        s0 += __shfl_xor_sync(0xffffffffu, s0, s);
                        s1 += __shfl_xor_sync(0xffffffffu, s1, s);
                    }
                    if (lane == 0) {
                        const float cx0 = s0 * inv, cx1 = s1 * inv;
                        ctxs[d] = cx0; ctxs[d + 1] = cx1;
                        __stcg(&g_x1[nxt][d * 64 + n], cx0);
                        __stcg(&g_x1[nxt][(d + 1) * 64 + n], cx1);
                    }
                }
            }
            __syncthreads();

            {
                const float4 h0 = *reinterpret_cast<const float4*>(&h2s[lane * 4]);
                const float4 c0 = *reinterpret_cast<const float4*>(&ctxs[lane * 4]);
                for (int v = wid; v < V_V; v += 16) {
                    const float4* er = reinterpret_cast<const float4*>(emb + (size_t)v * E_E);
                    const float4 e0 = er[lane], e1 = er[lane + 32];
                    float d = e0.x * h0.x + e0.y * h0.y + e0.z * h0.z + e0.w * h0.w
                            + e1.x * c0.x + e1.y * c0.y + e1.z * c0.z + e1.w * c0.w;
#pragma unroll
                    for (int s = 16; s > 0; s >>= 1) d += __shfl_xor_sync(0xffffffffu, d, s);
                    if (lane == 0) out[((size_t)n * L_L + step) * V_V + v] = d + bout[v];
                }
            }
        } else {
            // pre1 = W1h @ h1(step), consumed at A(step+1). 64 blocks x 8 j.
            const int j0 = (b - 64) * 8;
            const int ks = tid >> 7;        // 0..3 (128 k each)
            const int jl = (tid >> 4) & 7;  // 0..7
            const int nq = tid & 15;
            const int j = j0 + jl;
            const float4* __restrict__ h14 = reinterpret_cast<const float4*>(g_h1);
            unsigned long long acc[8];
#pragma unroll
            for (int i = 0; i < 8; i++) acc[i] = 0ull;
            for (int kc = 0; kc < 128; kc += 8) {
                float4 xv[8];
#pragma unroll
                for (int i = 0; i < 8; i++)
                    xv[i] = __ldcg(&h14[(ks * 128 + kc + i) * 16 + nq]);
#pragma unroll
                for (int i = 0; i < 8; i++) {
                    const int k = ks * 128 + kc + i;
                    const float4 w4 = *reinterpret_cast<const float4*>(&g_W1h[((size_t)k * 512 + j) * 4]);
                    const unsigned long long xlo = packf2(xv[i].x, xv[i].y);
                    const unsigned long long xhi = packf2(xv[i].z, xv[i].w);
                    acc[0] = f2fma(packf2(w4.x, w4.x), xlo, acc[0]);
                    acc[1] = f2fma(packf2(w4.x, w4.x), xhi, acc[1]);
                    acc[2] = f2fma(packf2(w4.y, w4.y), xlo, acc[2]);
                    acc[3] = f2fma(packf2(w4.y, w4.y), xhi, acc[3]);
                    acc[4] = f2fma(packf2(w4.z, w4.z), xlo, acc[4]);
                    acc[5] = f2fma(packf2(w4.z, w4.z), xhi, acc[5]);
                    acc[6] = f2fma(packf2(w4.w, w4.w), xlo, acc[6]);
                    acc[7] = f2fma(packf2(w4.w, w4.w), xhi, acc[7]);
                }
            }
#pragma unroll
            for (int g = 0; g < 4; g++) {
                float2 lo = *reinterpret_cast<float2*>(&acc[g * 2]);
                float2 hi = *reinterpret_cast<float2*>(&acc[g * 2 + 1]);
                *reinterpret_cast<float4*>(&cb[((ks * 8 + jl) * 4 + g) * 64 + nq * 4]) =
                    make_float4(lo.x, lo.y, hi.x, hi.y);
            }
            __syncthreads();
            {
                const int jl2 = tid >> 6, n = tid & 63;
                const int j2 = j0 + jl2;
#pragma unroll
                for (int g = 0; g < 4; g++) {
                    float s = cb[((0 * 8 + jl2) * 4 + g) * 64 + n]
                            + cb[((1 * 8 + jl2) * 4 + g) * 64 + n]
                            + cb[((2 * 8 + jl2) * 4 + g) * 64 + n]
                            + cb[((3 * 8 + jl2) * 4 + g) * 64 + n];
                    __stcg(&g_pre1[(j2 * 4 + g) * 64 + n], s);
                }
            }
        }
        gridbar(bs);
    }
}

extern "C" void kernel_launch(void* const* d_in, const int* in_sizes, int n_in,
                              void* d_out, int out_size) {
    mega<<<NBLK, NTHR>>>(
        (const float*)d_in[0], (const float*)d_in[1], (const int*)d_in[2],
        (const int*)d_in[3], (const float*)d_in[4], (const float*)d_in[5],
        (const float*)d_in[6], (const float*)d_in[7], (const float*)d_in[8],
        (const float*)d_in[9], (const float*)d_in[10], (const float*)d_in[11],
        (const float*)d_in[12], (const float*)d_in[13], (float*)d_out);
}